// round 4
// baseline (speedup 1.0000x reference)
#include <cuda_runtime.h>

#define NN 8192
#define EE 16384

// Scratch (no device mallocs allowed) — zeroed every launch in phase0.
__device__ float g_u[EE];   // e[e] * (Ro^T a)[e]
__device__ float g_v[EE];   // e[e] * (Ri^T b)[e]
__device__ float g_a[NN];   // X . k0
__device__ float g_b[NN];   // X . k1
__device__ float g_c[NN];   // X . k2

// ---------------- Phase 0: tiny setup (a,b,c vectors; zero u,v) ----------------
__global__ void phase0(const float* __restrict__ X, const float* __restrict__ ker) {
    int i = blockIdx.x * blockDim.x + threadIdx.x;
    if (i < EE) { g_u[i] = 0.0f; g_v[i] = 0.0f; }
    if (i < NN) {
        float4 x = reinterpret_cast<const float4*>(X)[i];
        g_a[i] = x.x * ker[0] + x.y * ker[1] + x.z * ker[2]  + x.w * ker[3];
        g_b[i] = x.x * ker[4] + x.y * ker[5] + x.z * ker[6]  + x.w * ker[7];
        g_c[i] = x.x * ker[8] + x.y * ker[9] + x.z * ker[10] + x.w * ker[11];
    }
}

// ---------------- Phase 1: column reductions u = e.(Ro^T a), v = e.(Ri^T b) ----
// Each thread owns one column e; block covers 256 consecutive columns (fully
// coalesced 128B warp loads), blockIdx.y selects a 128-row chunk. Partial sums
// scaled by e[e] and accumulated with atomicAdd (32768 distinct addrs -> cheap REDG).
#define P1_CHUNK 128
__global__ void phase1(const float* __restrict__ Ri, const float* __restrict__ Ro,
                       const float* __restrict__ ev) {
    __shared__ float sa[P1_CHUNK], sb[P1_CHUNK];
    int tid = threadIdx.x;
    int e   = blockIdx.x * 256 + tid;
    int n0  = blockIdx.y * P1_CHUNK;
    if (tid < P1_CHUNK) {
        sa[tid] = g_a[n0 + tid];
        sb[tid] = g_b[n0 + tid];
    }
    __syncthreads();

    const float* ro = Ro + (size_t)n0 * EE + e;
    const float* ri = Ri + (size_t)n0 * EE + e;
    float so = 0.0f, si = 0.0f;
#pragma unroll 8
    for (int j = 0; j < P1_CHUNK; j++) {
        so += ro[(size_t)j * EE] * sa[j];
        si += ri[(size_t)j * EE] * sb[j];
    }
    float w = ev[e];
    atomicAdd(&g_u[e], w * so);
    atomicAdd(&g_v[e], w * si);
}

// ---------------- Phase 2: row reductions out = Ri.u + Ro.v + c ----------------
// One block per 4 rows: u4/v4 loaded once per chunk, reused across the 4 rows
// (cuts u/v L2 traffic 4x). float4 loads, 10 in flight per thread per iter.
#define RPB 4
__global__ void phase2(const float* __restrict__ Ri, const float* __restrict__ Ro,
                       float* __restrict__ out) {
    __shared__ float red[RPB][256];
    int tid = threadIdx.x;
    int n0  = blockIdx.x * RPB;

    float s[RPB];
#pragma unroll
    for (int r = 0; r < RPB; r++) s[r] = 0.0f;

    const float4* u4p = reinterpret_cast<const float4*>(g_u);
    const float4* v4p = reinterpret_cast<const float4*>(g_v);

#pragma unroll 4
    for (int it = 0; it < EE / (256 * 4); it++) {
        int e4 = it * 256 + tid;  // float4 index within the row
        float4 u4 = u4p[e4];
        float4 v4 = v4p[e4];
#pragma unroll
        for (int r = 0; r < RPB; r++) {
            float4 a4 = reinterpret_cast<const float4*>(Ri + (size_t)(n0 + r) * EE)[e4];
            float4 b4 = reinterpret_cast<const float4*>(Ro + (size_t)(n0 + r) * EE)[e4];
            s[r] += a4.x * u4.x + a4.y * u4.y + a4.z * u4.z + a4.w * u4.w
                  + b4.x * v4.x + b4.y * v4.y + b4.z * v4.z + b4.w * v4.w;
        }
    }

#pragma unroll
    for (int r = 0; r < RPB; r++) red[r][tid] = s[r];
    __syncthreads();
    for (int st = 128; st > 0; st >>= 1) {
        if (tid < st) {
#pragma unroll
            for (int r = 0; r < RPB; r++) red[r][tid] += red[r][tid + st];
        }
        __syncthreads();
    }
    if (tid < RPB) out[n0 + tid] = red[tid][0] + g_c[n0 + tid];
}

extern "C" void kernel_launch(void* const* d_in, const int* in_sizes, int n_in,
                              void* d_out, int out_size) {
    const float* X   = (const float*)d_in[0];
    const float* ev  = (const float*)d_in[1];
    const float* Ri  = (const float*)d_in[2];
    const float* Ro  = (const float*)d_in[3];
    const float* ker = (const float*)d_in[4];
    float* out = (float*)d_out;

    phase0<<<EE / 256, 256>>>(X, ker);
    dim3 g1(EE / 256, NN / P1_CHUNK);
    phase1<<<g1, 256>>>(Ri, Ro, ev);
    phase2<<<NN / RPB, 256>>>(Ri, Ro, out);
}